// round 5
// baseline (speedup 1.0000x reference)
#include <cuda_runtime.h>
#include <cstdint>

// Geometric product in Cl(3,0,1): out[n,k] = sum_{i,j} a[n,i] b[n,j] C[i,j,k]
// Structure constants baked in at compile time (metric = 1,1,1,0).
//
// R5 = R4 with the quad-mapping bug fixed: smem is LINEAR (TMA-written), so
// the permuted access order u = v ^ ((t>>1)&3) is only an issue-order
// bank-conflict trick; register slots must be indexed by u (physical==logical).

static __host__ __device__ constexpr int cayley_sign(int A, int B) {
    if (A & B & 8) return 0;            // degenerate generator e3 (metric 0)
    int s = 0;
    int sa = A >> 1;
    while (sa) {
        int x = sa & B;
        while (x) { s += 1; x &= (x - 1); }
        sa >>= 1;
    }
    return (s & 1) ? -1 : 1;
}

static __device__ __forceinline__ uint32_t smem_u32(const void* p) {
    return (uint32_t)__cvta_generic_to_shared(p);
}

__global__ void __launch_bounds__(256, 4)
gp_kernel(const float* __restrict__ ag,
          const float* __restrict__ bg,
          float* __restrict__ og,
          int n_rows) {
    __shared__ __align__(16) float4 sa[1024];   // 16 KB, reused for output
    __shared__ __align__(16) float4 sb[1024];   // 16 KB
    __shared__ __align__(8)  uint64_t mbar;

    const int t    = threadIdx.x;
    const int row0 = blockIdx.x * 256;
    const bool full_tile = (row0 + 256 <= n_rows);

    constexpr uint32_t TILE_BYTES = 256 * 16 * 4;   // 16384

    if (full_tile) {
        // ---- TMA bulk load: gmem -> smem (linear), mbarrier-completed ----
        if (t == 0) {
            const uint32_t mb = smem_u32(&mbar);
            asm volatile("mbarrier.init.shared.b64 [%0], 1;" :: "r"(mb) : "memory");
            asm volatile("fence.proxy.async.shared::cta;" ::: "memory");
            asm volatile("mbarrier.arrive.expect_tx.shared.b64 _, [%0], %1;"
                         :: "r"(mb), "r"(2 * TILE_BYTES) : "memory");
            asm volatile(
                "cp.async.bulk.shared::cta.global.mbarrier::complete_tx::bytes "
                "[%0], [%1], %2, [%3];"
                :: "r"(smem_u32(sa)),
                   "l"(ag + (size_t)row0 * 16),
                   "r"(TILE_BYTES), "r"(mb) : "memory");
            asm volatile(
                "cp.async.bulk.shared::cta.global.mbarrier::complete_tx::bytes "
                "[%0], [%1], %2, [%3];"
                :: "r"(smem_u32(sb)),
                   "l"(bg + (size_t)row0 * 16),
                   "r"(TILE_BYTES), "r"(mb) : "memory");
        }
        __syncthreads();   // mbarrier init visible to all before waiting

        {
            const uint32_t mb = smem_u32(&mbar);
            uint32_t done;
            do {
                asm volatile(
                    "{\n\t.reg .pred p;\n\t"
                    "mbarrier.try_wait.parity.shared.b64 p, [%1], 0;\n\t"
                    "selp.b32 %0, 1, 0, p;\n\t}"
                    : "=r"(done) : "r"(mb) : "memory");
            } while (!done);
        }

        // ---- Read own row. Linear layout: physical quad u == logical quad u.
        //      Issue order permuted (u = v ^ p) for bank-conflict freedom. ----
        const int p = (t >> 1) & 3;
        float a[16], b[16];
        #pragma unroll
        for (int v = 0; v < 4; ++v) {
            const int u = v ^ p;
            const float4 va = sa[(t << 2) | u];
            const float4 vb = sb[(t << 2) | u];
            a[u * 4 + 0] = va.x; a[u * 4 + 1] = va.y;
            a[u * 4 + 2] = va.z; a[u * 4 + 3] = va.w;
            b[u * 4 + 0] = vb.x; b[u * 4 + 1] = vb.y;
            b[u * 4 + 2] = vb.z; b[u * 4 + 3] = vb.w;
        }

        // ---- 192 straight-line FFMAs ----
        float c[16];
        #pragma unroll
        for (int k = 0; k < 16; ++k) c[k] = 0.0f;
        #pragma unroll
        for (int A = 0; A < 16; ++A) {
            #pragma unroll
            for (int B = 0; B < 16; ++B) {
                const int sg = cayley_sign(A, B);
                if (sg == 1)       c[A ^ B] = fmaf( a[A], b[B], c[A ^ B]);
                else if (sg == -1) c[A ^ B] = fmaf(-a[A], b[B], c[A ^ B]);
            }
        }

        // ---- Own row back into sa (physical quad u gets logical quad u) ----
        #pragma unroll
        for (int v = 0; v < 4; ++v) {
            const int u = v ^ p;
            sa[(t << 2) | u] = make_float4(c[u * 4 + 0], c[u * 4 + 1],
                                           c[u * 4 + 2], c[u * 4 + 3]);
        }
        __syncthreads();

        // ---- TMA bulk store: smem -> gmem ----
        if (t == 0) {
            asm volatile("fence.proxy.async.shared::cta;" ::: "memory");
            asm volatile(
                "cp.async.bulk.global.shared::cta.bulk_group [%0], [%1], %2;"
                :: "l"(og + (size_t)row0 * 16),
                   "r"(smem_u32(sa)), "r"(TILE_BYTES) : "memory");
            asm volatile("cp.async.bulk.commit_group;" ::: "memory");
            asm volatile("cp.async.bulk.wait_group 0;" ::: "memory");
        }
    } else {
        // ---- Tail fallback (never taken for BATCH = 2^21): scalar path ----
        const int row = row0 + t;
        if (row < n_rows) {
            float a[16], b[16], c[16];
            #pragma unroll
            for (int k = 0; k < 16; ++k) {
                a[k] = ag[(size_t)row * 16 + k];
                b[k] = bg[(size_t)row * 16 + k];
                c[k] = 0.0f;
            }
            #pragma unroll
            for (int A = 0; A < 16; ++A) {
                #pragma unroll
                for (int B = 0; B < 16; ++B) {
                    const int sg = cayley_sign(A, B);
                    if (sg == 1)       c[A ^ B] = fmaf( a[A], b[B], c[A ^ B]);
                    else if (sg == -1) c[A ^ B] = fmaf(-a[A], b[B], c[A ^ B]);
                }
            }
            #pragma unroll
            for (int k = 0; k < 16; ++k)
                og[(size_t)row * 16 + k] = c[k];
        }
    }
}

extern "C" void kernel_launch(void* const* d_in, const int* in_sizes, int n_in,
                              void* d_out, int out_size) {
    const float* ag = (const float*)d_in[0];
    const float* bg = (const float*)d_in[1];
    // d_in[2] is the Cayley tensor; values are baked in at compile time.
    float* og = (float*)d_out;

    const int n_rows = in_sizes[0] / 16;
    const int blocks = (n_rows + 255) / 256;
    gp_kernel<<<blocks, 256>>>(ag, bg, og, n_rows);
}

// round 6
// speedup vs baseline: 3.5003x; 3.5003x over previous
#include <cuda_runtime.h>
#include <cstdint>

// Geometric product in Cl(3,0,1): out[n,k] = sum_{i,j} a[n,i] b[n,j] C[i,j,k]
// Structure constants baked in at compile time (metric = 1,1,1,0).
//
// R6 = R2 skeleton (best: 63.5us) with input staging switched from
// LDG.128+STS.128 to cp.async.cg (LDGSTS): L2 -> smem direct, no L1
// allocation, no register round-trip. Completion via wait_group +
// __syncthreads (no mbarrier polling — R5's failure mode).

static __host__ __device__ constexpr int cayley_sign(int A, int B) {
    if (A & B & 8) return 0;            // degenerate generator e3 (metric 0)
    int s = 0;
    int sa = A >> 1;
    while (sa) {
        int x = sa & B;
        while (x) { s += 1; x &= (x - 1); }
        sa >>= 1;
    }
    return (s & 1) ? -1 : 1;
}

// Swizzled position for flat float4 index idx within a 1024-float4 tile:
//   r = idx>>2 (row), c = idx&3 (quad); pos = 4r | (c ^ ((r>>1)&3))
// Conflict-free for both unit-stride staging and per-row access.
static __device__ __forceinline__ int swz(int idx) {
    const int r = idx >> 2;
    const int c = idx & 3;
    return (r << 2) | (c ^ ((r >> 1) & 3));
}

static __device__ __forceinline__ uint32_t smem_u32(const void* p) {
    return (uint32_t)__cvta_generic_to_shared(p);
}

static __device__ __forceinline__ void cp_async16(uint32_t dst, const void* src) {
    asm volatile("cp.async.cg.shared.global [%0], [%1], 16;"
                 :: "r"(dst), "l"(src) : "memory");
}

__global__ void __launch_bounds__(256)
gp_kernel(const float4* __restrict__ a4,
          const float4* __restrict__ b4,
          float4* __restrict__ o4,
          int n_rows) {
    __shared__ __align__(16) float4 sa[1024];   // 16 KB, reused for output
    __shared__ __align__(16) float4 sb[1024];   // 16 KB

    const int t     = threadIdx.x;
    const int base4 = blockIdx.x * 1024;
    const int row0  = blockIdx.x * 256;
    const bool full_tile = (row0 + 256 <= n_rows);

    // ---- Stage a and b: cp.async unit-stride gmem -> swizzled smem ----
    if (full_tile) {
        #pragma unroll
        for (int v = 0; v < 4; ++v) {
            const int idx = v * 256 + t;
            const uint32_t pa = smem_u32(&sa[swz(idx)]);
            const uint32_t pb = smem_u32(&sb[swz(idx)]);
            cp_async16(pa, &a4[base4 + idx]);
            cp_async16(pb, &b4[base4 + idx]);
        }
    } else {
        #pragma unroll
        for (int v = 0; v < 4; ++v) {
            const int idx = v * 256 + t;
            const int pos = swz(idx);
            if ((base4 + idx) < n_rows * 4) {
                cp_async16(smem_u32(&sa[pos]), &a4[base4 + idx]);
                cp_async16(smem_u32(&sb[pos]), &b4[base4 + idx]);
            } else {
                sa[pos] = make_float4(0.f, 0.f, 0.f, 0.f);
                sb[pos] = make_float4(0.f, 0.f, 0.f, 0.f);
            }
        }
    }
    asm volatile("cp.async.commit_group;" ::: "memory");
    asm volatile("cp.async.wait_group 0;" ::: "memory");
    __syncthreads();

    // ---- Each thread reads its own row (conflict-free via swizzle) ----
    float a[16], b[16];
    const int s = (t >> 1) & 3;
    #pragma unroll
    for (int v = 0; v < 4; ++v) {
        const int u = v ^ s;                       // physical quad holding logical quad v
        const float4 va = sa[(t << 2) | u];
        const float4 vb = sb[(t << 2) | u];
        a[v * 4 + 0] = va.x; a[v * 4 + 1] = va.y;
        a[v * 4 + 2] = va.z; a[v * 4 + 3] = va.w;
        b[v * 4 + 0] = vb.x; b[v * 4 + 1] = vb.y;
        b[v * 4 + 2] = vb.z; b[v * 4 + 3] = vb.w;
    }

    // ---- 192 straight-line FFMAs ----
    float c[16];
    #pragma unroll
    for (int k = 0; k < 16; ++k) c[k] = 0.0f;

    #pragma unroll
    for (int A = 0; A < 16; ++A) {
        #pragma unroll
        for (int B = 0; B < 16; ++B) {
            const int sg = cayley_sign(A, B);
            if (sg == 1) {
                c[A ^ B] = fmaf(a[A], b[B], c[A ^ B]);
            } else if (sg == -1) {
                c[A ^ B] = fmaf(-a[A], b[B], c[A ^ B]);
            }
        }
    }

    // ---- Write own output row into sa (own region; no pre-sync needed) ----
    #pragma unroll
    for (int v = 0; v < 4; ++v) {
        const int u = v ^ s;
        sa[(t << 2) | u] = make_float4(c[v * 4 + 0], c[v * 4 + 1],
                                       c[v * 4 + 2], c[v * 4 + 3]);
    }
    __syncthreads();

    // ---- Gather + unit-stride global stores ----
    if (full_tile) {
        #pragma unroll
        for (int v = 0; v < 4; ++v) {
            const int idx = v * 256 + t;
            o4[base4 + idx] = sa[swz(idx)];
        }
    } else {
        #pragma unroll
        for (int v = 0; v < 4; ++v) {
            const int idx = v * 256 + t;
            if ((base4 + idx) < n_rows * 4)
                o4[base4 + idx] = sa[swz(idx)];
        }
    }
}

extern "C" void kernel_launch(void* const* d_in, const int* in_sizes, int n_in,
                              void* d_out, int out_size) {
    const float4* a4 = (const float4*)d_in[0];
    const float4* b4 = (const float4*)d_in[1];
    // d_in[2] is the Cayley tensor; values are baked in at compile time.
    float4* o4 = (float4*)d_out;

    const int n_rows = in_sizes[0] / 16;
    const int blocks = (n_rows + 255) / 256;
    gp_kernel<<<blocks, 256>>>(a4, b4, o4, n_rows);
}